// round 1
// baseline (speedup 1.0000x reference)
#include <cuda_runtime.h>

#define D      256
#define B      1024
#define FOURD  1024
#define TWO_D  512
#define KDIM   512
#define NITER  6

// ---------------- scratch (device globals; no allocation allowed) ----------------
__device__ float g_h[B * D];
__device__ float g_c[B * D];
__device__ float g_gates[B * FOURD];        // 4 MB
__device__ float g_Wp[FOURD * KDIM];        // 2 MB combined weight
__device__ float g_bc[FOURD];
__device__ int   g_segstart[B + 1];

// ---------------- init: h=0, c=0, q_star(out)=0 ----------------
__global__ void zero_kernel(float* __restrict__ out) {
    int i = blockIdx.x * blockDim.x + threadIdx.x;
    if (i < B * D) { g_h[i] = 0.f; g_c[i] = 0.f; }
    if (i < B * TWO_D) out[i] = 0.f;
}

// ---------------- prep: W' = [Wih[:, :D] + Whh | Wih[:, D:]],  bc = bih + bhh ----
__global__ void prep_kernel(const float* __restrict__ Wih,
                            const float* __restrict__ Whh,
                            const float* __restrict__ bih,
                            const float* __restrict__ bhh) {
    int idx = blockIdx.x * blockDim.x + threadIdx.x;
    if (idx >= FOURD * KDIM) return;
    int r = idx >> 9;        // row in [0, 4D)
    int k = idx & (KDIM - 1);
    float w = Wih[idx];
    if (k < D) w += Whh[r * D + k];
    g_Wp[idx] = w;
    if (idx < FOURD) g_bc[idx] = bih[idx] + bhh[idx];
}

// ---------------- segment boundaries from sorted segment_ids ----------------
__global__ void segstart_kernel(const int* __restrict__ seg, int n) {
    int i = blockIdx.x * blockDim.x + threadIdx.x;
    if (i >= n) return;
    int s  = seg[i];
    int sp = (i == 0) ? -1 : seg[i - 1];
    for (int t = sp + 1; t <= s; t++) g_segstart[t] = i;
    if (i == n - 1) {
        for (int t = s + 1; t <= B; t++) g_segstart[t] = n;
    }
}

// ---------------- gates = X @ W'^T + bc ;  X = q_star [B, 512] ----------------
// C[1024,1024], K=512. 64x64 tiles, 256 threads, 4x4 microtile, BK=16.
__global__ void gemm_kernel(const float* __restrict__ X) {
    __shared__ __align__(16) float As[16][68];
    __shared__ __align__(16) float Bs[16][68];
    const int m0 = blockIdx.y * 64;
    const int n0 = blockIdx.x * 64;
    const int tid  = threadIdx.x;
    const int lrow = tid >> 2;           // 0..63
    const int lcol = (tid & 3) << 2;     // 0,4,8,12
    const int tx = tid & 15, ty = tid >> 4;

    float acc[4][4] = {};
    const float* xp = X     + (size_t)(m0 + lrow) * KDIM + lcol;
    const float* wp = g_Wp  + (size_t)(n0 + lrow) * KDIM + lcol;

    for (int kt = 0; kt < KDIM; kt += 16) {
        float4 xv = *(const float4*)(xp + kt);
        float4 wv = *(const float4*)(wp + kt);
        As[lcol + 0][lrow] = xv.x; As[lcol + 1][lrow] = xv.y;
        As[lcol + 2][lrow] = xv.z; As[lcol + 3][lrow] = xv.w;
        Bs[lcol + 0][lrow] = wv.x; Bs[lcol + 1][lrow] = wv.y;
        Bs[lcol + 2][lrow] = wv.z; Bs[lcol + 3][lrow] = wv.w;
        __syncthreads();
#pragma unroll
        for (int kk = 0; kk < 16; kk++) {
            float4 a = *(const float4*)&As[kk][ty * 4];
            float4 b = *(const float4*)&Bs[kk][tx * 4];
            float av[4] = {a.x, a.y, a.z, a.w};
            float bv[4] = {b.x, b.y, b.z, b.w};
#pragma unroll
            for (int i2 = 0; i2 < 4; i2++)
#pragma unroll
                for (int j2 = 0; j2 < 4; j2++)
                    acc[i2][j2] += av[i2] * bv[j2];
        }
        __syncthreads();
    }
#pragma unroll
    for (int i2 = 0; i2 < 4; i2++) {
        int row = m0 + ty * 4 + i2;
        int col = n0 + tx * 4;
        float4 o;
        o.x = acc[i2][0] + g_bc[col + 0];
        o.y = acc[i2][1] + g_bc[col + 1];
        o.z = acc[i2][2] + g_bc[col + 2];
        o.w = acc[i2][3] + g_bc[col + 3];
        *(float4*)&g_gates[(size_t)row * FOURD + col] = o;
    }
}

// ---------------- LSTM pointwise: gate order i,f,g,o ----------------
__device__ __forceinline__ float sigf(float x) { return 1.f / (1.f + __expf(-x)); }

__global__ void lstm_kernel() {
    int idx = blockIdx.x * blockDim.x + threadIdx.x;
    if (idx >= B * D) return;
    int b = idx >> 8;
    int j = idx & 255;
    const float* gr = g_gates + (size_t)b * FOURD;
    float gi = gr[j], gf = gr[j + D], gg = gr[j + 2 * D], go = gr[j + 3 * D];
    float c = sigf(gf) * g_c[idx] + sigf(gi) * tanhf(gg);
    float h = sigf(go) * tanhf(c);
    g_c[idx] = c;
    g_h[idx] = h;
}

// ---------------- fused attention: e -> online segment softmax -> readout -----
// One block per graph; thread d owns feature dim d. Single pass over feat.
__global__ void attn_kernel(const float* __restrict__ feat, float* __restrict__ qstar) {
    __shared__ float red[4][8];
    const int g    = blockIdx.x;
    const int d    = threadIdx.x;
    const int warp = d >> 5, lane = d & 31;
    const int s0 = g_segstart[g];
    const int s1 = g_segstart[g + 1];
    const float qd = g_h[g * D + d];

    float m = -1e30f, ssum = 0.f, acc = 0.f;

    for (int i = s0; i < s1; i += 4) {
        const int cnt = min(4, s1 - i);
        float v[4], p[4];
#pragma unroll
        for (int j = 0; j < 4; j++) {
            v[j] = (j < cnt) ? feat[(size_t)(i + j) * D + d] : 0.f;
            p[j] = v[j] * qd;
        }
        // 4 interleaved warp reductions (hide shfl latency)
#pragma unroll
        for (int o = 16; o > 0; o >>= 1)
#pragma unroll
            for (int j = 0; j < 4; j++)
                p[j] += __shfl_down_sync(0xffffffffu, p[j], o);
        if (lane == 0) {
            red[0][warp] = p[0]; red[1][warp] = p[1];
            red[2][warp] = p[2]; red[3][warp] = p[3];
        }
        __syncthreads();
        float e[4];
#pragma unroll
        for (int j = 0; j < 4; j++) {
            float t = 0.f;
#pragma unroll
            for (int w = 0; w < 8; w++) t += red[j][w];
            e[j] = (j < cnt) ? t : -1e30f;
        }
        __syncthreads();
        // online softmax update
        float mnew = m;
#pragma unroll
        for (int j = 0; j < 4; j++) mnew = fmaxf(mnew, e[j]);
        float sc = __expf(m - mnew);
        ssum *= sc; acc *= sc; m = mnew;
#pragma unroll
        for (int j = 0; j < 4; j++) {
            float w = __expf(e[j] - m);
            ssum += w;
            acc  += w * v[j];
        }
    }

    float r = (s1 > s0) ? acc / ssum : 0.f;
    qstar[(size_t)g * TWO_D + d]     = qd;   // q half
    qstar[(size_t)g * TWO_D + D + d] = r;    // readout half
}

// ---------------- driver ----------------
extern "C" void kernel_launch(void* const* d_in, const int* in_sizes, int n_in,
                              void* d_out, int out_size) {
    const float* feat = (const float*)d_in[0];
    const float* Wih  = (const float*)d_in[1];
    const float* Whh  = (const float*)d_in[2];
    const float* bih  = (const float*)d_in[3];
    const float* bhh  = (const float*)d_in[4];
    const int*   seg  = (const int*)d_in[5];
    const int n = in_sizes[0] / D;   // number of nodes
    float* out = (float*)d_out;      // q_star [B, 2D] lives here

    zero_kernel<<<(B * TWO_D + 255) / 256, 256>>>(out);
    prep_kernel<<<(FOURD * KDIM + 255) / 256, 256>>>(Wih, Whh, bih, bhh);
    segstart_kernel<<<(n + 255) / 256, 256>>>(seg, n);

    for (int it = 0; it < NITER; it++) {
        gemm_kernel<<<dim3(16, 16), 256>>>(out);   // gates from q_star
        lstm_kernel<<<(B * D + 255) / 256, 256>>>();
        attn_kernel<<<B, 256>>>(feat, out);        // writes new q_star
    }
}

// round 2
// speedup vs baseline: 1.7243x; 1.7243x over previous
#include <cuda_runtime.h>

#define D      256
#define B      1024
#define FOURD  1024
#define TWO_D  512
#define KDIM   512
#define NITER  6

// ---------------- scratch (device globals; no allocation allowed) ----------------
__device__ float g_h[B * D];
__device__ float g_c[B * D];
__device__ float g_gates[B * FOURD];        // 4 MB
__device__ float g_Wp[FOURD * KDIM];        // 2 MB combined weight
__device__ float g_bc[FOURD];
__device__ int   g_segstart[B + 1];

// ---------------- init: h=0, c=0, q_star(out)=0 ----------------
__global__ void zero_kernel(float* __restrict__ out) {
    int i = blockIdx.x * blockDim.x + threadIdx.x;
    if (i < B * D) { g_h[i] = 0.f; g_c[i] = 0.f; }
    if (i < B * TWO_D) out[i] = 0.f;
}

// ---------------- prep: W' = [Wih[:, :D] + Whh | Wih[:, D:]],  bc = bih + bhh ----
__global__ void prep_kernel(const float* __restrict__ Wih,
                            const float* __restrict__ Whh,
                            const float* __restrict__ bih,
                            const float* __restrict__ bhh) {
    int idx = blockIdx.x * blockDim.x + threadIdx.x;
    if (idx >= FOURD * KDIM) return;
    int r = idx >> 9;        // row in [0, 4D)
    int k = idx & (KDIM - 1);
    float w = Wih[idx];
    if (k < D) w += Whh[r * D + k];
    g_Wp[idx] = w;
    if (idx < FOURD) g_bc[idx] = bih[idx] + bhh[idx];
}

// ---------------- segment boundaries from sorted segment_ids ----------------
__global__ void segstart_kernel(const int* __restrict__ seg, int n) {
    int i = blockIdx.x * blockDim.x + threadIdx.x;
    if (i >= n) return;
    int s  = seg[i];
    int sp = (i == 0) ? -1 : seg[i - 1];
    for (int t = sp + 1; t <= s; t++) g_segstart[t] = i;
    if (i == n - 1) {
        for (int t = s + 1; t <= B; t++) g_segstart[t] = n;
    }
}

// ---------------- gates = X @ W'^T + bc ;  X = q_star [B, 512] ----------------
// C[1024,1024], K=512. 64x64 tiles, 256 threads, 4x4 microtile, BK=32.
__global__ __launch_bounds__(256) void gemm_kernel(const float* __restrict__ X) {
    __shared__ __align__(16) float As[32][68];
    __shared__ __align__(16) float Bs[32][68];
    const int m0 = blockIdx.y * 64;
    const int n0 = blockIdx.x * 64;
    const int tid  = threadIdx.x;
    const int lrow = tid >> 2;           // 0..63
    const int lcol = (tid & 3) << 2;     // 0,4,8,12
    const int tx = tid & 15, ty = tid >> 4;

    float acc[4][4] = {};
    const float* xp = X     + (size_t)(m0 + lrow) * KDIM + lcol;
    const float* wp = g_Wp  + (size_t)(n0 + lrow) * KDIM + lcol;

    for (int kt = 0; kt < KDIM; kt += 32) {
        float4 xv0 = *(const float4*)(xp + kt);
        float4 xv1 = *(const float4*)(xp + kt + 16);
        float4 wv0 = *(const float4*)(wp + kt);
        float4 wv1 = *(const float4*)(wp + kt + 16);
        As[lcol + 0][lrow] = xv0.x; As[lcol + 1][lrow] = xv0.y;
        As[lcol + 2][lrow] = xv0.z; As[lcol + 3][lrow] = xv0.w;
        As[lcol + 16][lrow] = xv1.x; As[lcol + 17][lrow] = xv1.y;
        As[lcol + 18][lrow] = xv1.z; As[lcol + 19][lrow] = xv1.w;
        Bs[lcol + 0][lrow] = wv0.x; Bs[lcol + 1][lrow] = wv0.y;
        Bs[lcol + 2][lrow] = wv0.z; Bs[lcol + 3][lrow] = wv0.w;
        Bs[lcol + 16][lrow] = wv1.x; Bs[lcol + 17][lrow] = wv1.y;
        Bs[lcol + 18][lrow] = wv1.z; Bs[lcol + 19][lrow] = wv1.w;
        __syncthreads();
#pragma unroll
        for (int kk = 0; kk < 32; kk++) {
            float4 a = *(const float4*)&As[kk][ty * 4];
            float4 b = *(const float4*)&Bs[kk][tx * 4];
            float av[4] = {a.x, a.y, a.z, a.w};
            float bv[4] = {b.x, b.y, b.z, b.w};
#pragma unroll
            for (int i2 = 0; i2 < 4; i2++)
#pragma unroll
                for (int j2 = 0; j2 < 4; j2++)
                    acc[i2][j2] = fmaf(av[i2], bv[j2], acc[i2][j2]);
        }
        __syncthreads();
    }
#pragma unroll
    for (int i2 = 0; i2 < 4; i2++) {
        int row = m0 + ty * 4 + i2;
        int col = n0 + tx * 4;
        float4 o;
        o.x = acc[i2][0] + g_bc[col + 0];
        o.y = acc[i2][1] + g_bc[col + 1];
        o.z = acc[i2][2] + g_bc[col + 2];
        o.w = acc[i2][3] + g_bc[col + 3];
        *(float4*)&g_gates[(size_t)row * FOURD + col] = o;
    }
}

// ---------------- LSTM pointwise: gate order i,f,g,o ----------------
__device__ __forceinline__ float sigf(float x) { return 1.f / (1.f + __expf(-x)); }

__global__ void lstm_kernel() {
    int idx = blockIdx.x * blockDim.x + threadIdx.x;
    if (idx >= B * D) return;
    int b = idx >> 8;
    int j = idx & 255;
    const float* gr = g_gates + (size_t)b * FOURD;
    float gi = gr[j], gf = gr[j + D], gg = gr[j + 2 * D], go = gr[j + 3 * D];
    float c = sigf(gf) * g_c[idx] + sigf(gi) * tanhf(gg);
    float h = sigf(go) * tanhf(c);
    g_c[idx] = c;
    g_h[idx] = h;
}

// ---------------- fused attention v2: barrier-free warp-local online softmax ----
// One block (8 warps) per graph. Warp w owns nodes s0+w, s0+w+8, ... Each warp
// keeps its own online-softmax state (m, ssum, acc lane-distributed 8 dims/lane).
// No block barriers in the mainloop; single 8-way merge at the end.
__global__ __launch_bounds__(256) void attn_kernel(const float* __restrict__ feat,
                                                   float* __restrict__ qstar) {
    __shared__ float s_m[8], s_s[8];
    __shared__ float s_acc[8][256];
    const int g    = blockIdx.x;
    const int tid  = threadIdx.x;
    const int w    = tid >> 5, lane = tid & 31;
    const int s0 = g_segstart[g];
    const int s1 = g_segstart[g + 1];

    // per-lane q slice: lane holds dims [lane*8, lane*8+8)
    float q[8];
    {
        const float* qp = g_h + (size_t)g * D + lane * 8;
#pragma unroll
        for (int j = 0; j < 8; j++) q[j] = qp[j];
    }

    float m = -1e30f, ss = 0.f;
    float acc[8] = {};

    int i = s0 + w;
    // pairwise mainloop: interleave two shuffle-reduction chains, MLP=4 on loads
    for (; i + 8 < s1; i += 16) {
        const float* pa_ = feat + (size_t)i * D + lane * 8;
        const float* pb_ = feat + (size_t)(i + 8) * D + lane * 8;
        float4 a0 = *(const float4*)(pa_);
        float4 a1 = *(const float4*)(pa_ + 4);
        float4 b0 = *(const float4*)(pb_);
        float4 b1 = *(const float4*)(pb_ + 4);
        float va[8] = {a0.x, a0.y, a0.z, a0.w, a1.x, a1.y, a1.z, a1.w};
        float vb[8] = {b0.x, b0.y, b0.z, b0.w, b1.x, b1.y, b1.z, b1.w};
        float pa = 0.f, pb = 0.f;
#pragma unroll
        for (int j = 0; j < 8; j++) {
            pa = fmaf(va[j], q[j], pa);
            pb = fmaf(vb[j], q[j], pb);
        }
#pragma unroll
        for (int o = 16; o > 0; o >>= 1) {
            pa += __shfl_xor_sync(0xffffffffu, pa, o);
            pb += __shfl_xor_sync(0xffffffffu, pb, o);
        }
        float mn = fmaxf(m, fmaxf(pa, pb));
        float sc = __expf(m - mn);
        float wa = __expf(pa - mn);
        float wb = __expf(pb - mn);
        ss = ss * sc + wa + wb;
#pragma unroll
        for (int j = 0; j < 8; j++)
            acc[j] = fmaf(acc[j], sc, fmaf(wa, va[j], wb * vb[j]));
        m = mn;
    }
    if (i < s1) {   // tail node
        const float* pa_ = feat + (size_t)i * D + lane * 8;
        float4 a0 = *(const float4*)(pa_);
        float4 a1 = *(const float4*)(pa_ + 4);
        float va[8] = {a0.x, a0.y, a0.z, a0.w, a1.x, a1.y, a1.z, a1.w};
        float pa = 0.f;
#pragma unroll
        for (int j = 0; j < 8; j++) pa = fmaf(va[j], q[j], pa);
#pragma unroll
        for (int o = 16; o > 0; o >>= 1)
            pa += __shfl_xor_sync(0xffffffffu, pa, o);
        float mn = fmaxf(m, pa);
        float sc = __expf(m - mn);
        float wa = __expf(pa - mn);
        ss = ss * sc + wa;
#pragma unroll
        for (int j = 0; j < 8; j++)
            acc[j] = fmaf(acc[j], sc, wa * va[j]);
        m = mn;
    }

    // publish warp state
    if (lane == 0) { s_m[w] = m; s_s[w] = ss; }
#pragma unroll
    for (int j = 0; j < 8; j += 4)
        *(float4*)&s_acc[w][lane * 8 + j] = make_float4(acc[j], acc[j+1], acc[j+2], acc[j+3]);
    __syncthreads();

    // 8-way merge; thread d owns output dim d
    const int d = tid;
    float M = -1e30f;
#pragma unroll
    for (int t = 0; t < 8; t++) M = fmaxf(M, s_m[t]);
    float denom = 0.f, num = 0.f;
#pragma unroll
    for (int t = 0; t < 8; t++) {
        float sc = __expf(s_m[t] - M);
        denom += sc * s_s[t];
        num   += sc * s_acc[t][d];
    }
    float qd = g_h[(size_t)g * D + d];
    float r  = (s1 > s0) ? num / denom : 0.f;
    qstar[(size_t)g * TWO_D + d]     = qd;   // q half
    qstar[(size_t)g * TWO_D + D + d] = r;    // readout half
}

// ---------------- driver ----------------
extern "C" void kernel_launch(void* const* d_in, const int* in_sizes, int n_in,
                              void* d_out, int out_size) {
    const float* feat = (const float*)d_in[0];
    const float* Wih  = (const float*)d_in[1];
    const float* Whh  = (const float*)d_in[2];
    const float* bih  = (const float*)d_in[3];
    const float* bhh  = (const float*)d_in[4];
    const int*   seg  = (const int*)d_in[5];
    const int n = in_sizes[0] / D;   // number of nodes
    float* out = (float*)d_out;      // q_star [B, 2D] lives here

    zero_kernel<<<(B * TWO_D + 255) / 256, 256>>>(out);
    prep_kernel<<<(FOURD * KDIM + 255) / 256, 256>>>(Wih, Whh, bih, bhh);
    segstart_kernel<<<(n + 255) / 256, 256>>>(seg, n);

    for (int it = 0; it < NITER; it++) {
        gemm_kernel<<<dim3(16, 16), 256>>>(out);   // gates from q_star
        lstm_kernel<<<(B * D + 255) / 256, 256>>>();
        attn_kernel<<<B, 256>>>(feat, out);        // writes new q_star
    }
}

// round 6
// speedup vs baseline: 2.4149x; 1.4005x over previous
#include <cuda_runtime.h>
#include <cuda_bf16.h>
#include <cstdint>

#define D      256
#define B      1024
#define FOURD  1024
#define TWO_D  512
#define KDIM   512
#define NITER  6

// GEMM tiling
#define TILE_M   128
#define TILE_N   128
#define KCH      64          // bf16 K elems per chunk (128B per row)
#define CHUNKS   12          // chunks per K-half (virtual K = 1536 = 24 chunks, 2 halves)
#define STAGE_BYTES 32768    // A 16KB + B 16KB
#define SMEM_BYTES  (3 * STAGE_BYTES)   // 98304

// ---------------- scratch (device globals; no allocation allowed) ----------------
__device__ float g_h[B * D];                 // row-major [b][j]
__device__ float g_c[B * D];                 // row-major [b][j]
__device__ __nv_bfloat16 g_Xs[B * 1024];     // [row][0:512)=hi(X), [512:1024)=lo(X)
__device__ __nv_bfloat16 g_Ws[FOURD * 1024]; // [n][0:512)=hi(W'), [512:1024)=lo(W')
__device__ float g_PT[2 * B * FOURD];        // K-split partials, row-major [kh][m][n]
__device__ float g_bc[FOURD];
__device__ int   g_segstart[B + 1];

// ---------------- helpers ----------------
__device__ __forceinline__ uint32_t smem_u32(const void* p) {
    uint32_t a;
    asm("{ .reg .u64 t; cvta.to.shared.u64 t, %1; cvt.u32.u64 %0, t; }" : "=r"(a) : "l"(p));
    return a;
}
static __device__ __forceinline__ uint32_t swz128(uint32_t off) {
    return off ^ ((off >> 3) & 0x70);
}
__device__ __forceinline__ void cp16(uint32_t saddr, const void* gaddr) {
    asm volatile("cp.async.cg.shared.global [%0], [%1], 16;"
                 :: "r"(saddr), "l"(gaddr) : "memory");
}
#define CP_COMMIT() asm volatile("cp.async.commit_group;" ::: "memory")
#define CP_WAIT2()  asm volatile("cp.async.wait_group 2;" ::: "memory")
#define CP_WAIT1()  asm volatile("cp.async.wait_group 1;" ::: "memory")
#define CP_WAIT0()  asm volatile("cp.async.wait_group 0;" ::: "memory")

__device__ __forceinline__ void ldmx4(uint32_t& r0, uint32_t& r1, uint32_t& r2,
                                      uint32_t& r3, uint32_t addr) {
    asm volatile("ldmatrix.sync.aligned.m8n8.x4.shared.b16 {%0,%1,%2,%3}, [%4];"
                 : "=r"(r0), "=r"(r1), "=r"(r2), "=r"(r3) : "r"(addr));
}
__device__ __forceinline__ void mma16816(float* c, const uint32_t* a,
                                         uint32_t b0, uint32_t b1) {
    asm volatile("mma.sync.aligned.m16n8k16.row.col.f32.bf16.bf16.f32 "
                 "{%0,%1,%2,%3}, {%4,%5,%6,%7}, {%8,%9}, {%0,%1,%2,%3};"
                 : "+f"(c[0]), "+f"(c[1]), "+f"(c[2]), "+f"(c[3])
                 : "r"(a[0]), "r"(a[1]), "r"(a[2]), "r"(a[3]), "r"(b0), "r"(b1));
}

// ---------------- init: h=0, c=0, q_star(out)=0 ----------------
__global__ void zero_kernel(float* __restrict__ out) {
    int i = blockIdx.x * blockDim.x + threadIdx.x;
    if (i < B * D) { g_h[i] = 0.f; g_c[i] = 0.f; }
    if (i < B * TWO_D) out[i] = 0.f;
}

// ---------------- prep: W' = [Wih[:, :D]+Whh | Wih[:, D:]] -> bf16 hi/lo split ----
__global__ void prep_kernel(const float* __restrict__ Wih,
                            const float* __restrict__ Whh,
                            const float* __restrict__ bih,
                            const float* __restrict__ bhh) {
    int idx = blockIdx.x * blockDim.x + threadIdx.x;
    if (idx >= FOURD * KDIM) return;
    int r = idx >> 9;
    int k = idx & (KDIM - 1);
    float w = Wih[idx];
    if (k < D) w += Whh[r * D + k];
    __nv_bfloat16 hi = __float2bfloat16(w);
    __nv_bfloat16 lo = __float2bfloat16(w - __bfloat162float(hi));
    g_Ws[r * 1024 + k]       = hi;
    g_Ws[r * 1024 + 512 + k] = lo;
    if (idx < FOURD) g_bc[idx] = bih[idx] + bhh[idx];
}

// ---------------- per-iter: split q_star fp32 -> bf16 hi/lo ----------------
__global__ void split_kernel(const float* __restrict__ X) {
    int idx = blockIdx.x * blockDim.x + threadIdx.x;   // B*512 threads
    if (idx >= B * KDIM) return;
    int r = idx >> 9;
    int k = idx & (KDIM - 1);
    float x = X[idx];
    __nv_bfloat16 hi = __float2bfloat16(x);
    __nv_bfloat16 lo = __float2bfloat16(x - __bfloat162float(hi));
    g_Xs[r * 1024 + k]       = hi;
    g_Xs[r * 1024 + 512 + k] = lo;
}

// ---------------- segment boundaries from sorted segment_ids ----------------
__global__ void segstart_kernel(const int* __restrict__ seg, int n) {
    int i = blockIdx.x * blockDim.x + threadIdx.x;
    if (i >= n) return;
    int s  = seg[i];
    int sp = (i == 0) ? -1 : seg[i - 1];
    for (int t = sp + 1; t <= s; t++) g_segstart[t] = i;
    if (i == n - 1) {
        for (int t = s + 1; t <= B; t++) g_segstart[t] = n;
    }
}

// ---------------- mma.sync bf16 GEMM: PT[kh] partial of gates = Xs @ Ws^T --------
// Virtual K = 1536: [hiX|loX|hiX] . [hiW|hiW|loW]. 128 CTAs: 8 M x 8 N x 2 Khalf.
// 8 warps: 2 (M) x 4 (N); warp tile 64x32; 3-stage cp.async pipeline.
extern __shared__ char dsm[];
__global__ __launch_bounds__(256) void gemm_mma() {
    const int tid  = threadIdx.x;
    const int lane = tid & 31;
    const int wid  = tid >> 5;
    const int wm   = wid & 1;           // 0..1  -> m offset 64*wm
    const int wn   = wid >> 1;          // 0..3  -> n offset 32*wn
    const int bid  = blockIdx.x;
    const int nt = bid & 7, mt = (bid >> 3) & 7, kh = bid >> 6;
    const int m0 = mt * TILE_M, n0 = nt * TILE_N;
    const uint32_t sb = smem_u32(dsm);

    float acc[4][4][4] = {};            // [mi][ni][reg]

    // issue chunk cc's loads into stage cc%3 (8 cp.async per thread)
    auto issue = [&](int cc) {
        const int k0   = (kh * CHUNKS + cc) * KCH;
        const int acol = (k0 < 1024) ? k0 : k0 - 1024;   // col in g_Xs
        const int wcol = (k0 < 512)  ? k0 : k0 - 512;    // col in g_Ws
        const uint32_t stg = sb + (cc % 3) * STAGE_BYTES;
#pragma unroll
        for (int i = 0; i < 4; i++) {            // A: 128 rows x 128B
            int u = tid + i * 256;
            int row = u >> 3, c16 = u & 7;
            const char* gp = (const char*)g_Xs +
                             ((size_t)(m0 + row) * 1024 + acol) * 2 + c16 * 16;
            cp16(stg + swz128(row * 128 + c16 * 16), gp);
        }
#pragma unroll
        for (int i = 0; i < 4; i++) {            // B: 128 rows x 128B
            int u = tid + i * 256;
            int row = u >> 3, c16 = u & 7;
            const char* gp = (const char*)g_Ws +
                             ((size_t)(n0 + row) * 1024 + wcol) * 2 + c16 * 16;
            cp16(stg + 16384 + swz128(row * 128 + c16 * 16), gp);
        }
        CP_COMMIT();
    };

    issue(0); issue(1); issue(2);

    for (int cc = 0; cc < CHUNKS; cc++) {
        if (cc <= 9) CP_WAIT2();
        else if (cc == 10) CP_WAIT1();
        else CP_WAIT0();
        __syncthreads();

        const uint32_t sA = sb + (cc % 3) * STAGE_BYTES;
        const uint32_t sB = sA + 16384;

#pragma unroll
        for (int ks = 0; ks < 4; ks++) {        // 4 k16 steps per chunk
            const int c16b = ks * 2;
            uint32_t a[4][4], b[2][4];
#pragma unroll
            for (int mi = 0; mi < 4; mi++) {
                int row = wm * 64 + mi * 16 + (lane & 15);
                int c16 = c16b + (lane >> 4);
                ldmx4(a[mi][0], a[mi][1], a[mi][2], a[mi][3],
                      sA + swz128(row * 128 + c16 * 16));
            }
#pragma unroll
            for (int np = 0; np < 2; np++) {
                int row = wn * 32 + np * 16 + (lane & 7) + ((lane >> 4) & 1) * 8;
                int c16 = c16b + ((lane >> 3) & 1);
                ldmx4(b[np][0], b[np][1], b[np][2], b[np][3],
                      sB + swz128(row * 128 + c16 * 16));
            }
#pragma unroll
            for (int mi = 0; mi < 4; mi++)
#pragma unroll
                for (int ni = 0; ni < 4; ni++)
                    mma16816(acc[mi][ni], a[mi],
                             b[ni >> 1][(ni & 1) * 2], b[ni >> 1][(ni & 1) * 2 + 1]);
        }
        __syncthreads();
        if (cc + 3 < CHUNKS) issue(cc + 3);
    }

    // epilogue: row-major [kh][m][n]; c0,c1 = (row g, cols 2t,2t+1); c2,c3 = row g+8
    {
        const int g = lane >> 2, t = lane & 3;
        float* dst = g_PT + (size_t)kh * (B * FOURD);
#pragma unroll
        for (int mi = 0; mi < 4; mi++) {
            int row = m0 + wm * 64 + mi * 16 + g;
#pragma unroll
            for (int ni = 0; ni < 4; ni++) {
                int col = n0 + wn * 32 + ni * 8 + 2 * t;
                *(float2*)&dst[(size_t)row * FOURD + col] =
                    make_float2(acc[mi][ni][0], acc[mi][ni][1]);
                *(float2*)&dst[(size_t)(row + 8) * FOURD + col] =
                    make_float2(acc[mi][ni][2], acc[mi][ni][3]);
            }
        }
    }
}

// ---------------- LSTM pointwise (sums K-split partials, adds bias) ------------
__device__ __forceinline__ float sigf(float x) { return 1.f / (1.f + __expf(-x)); }

__global__ void lstm_kernel() {
    int t = blockIdx.x * blockDim.x + threadIdx.x;
    if (t >= B * D) return;
    int b = t >> 8;           // batch row
    int j = t & 255;          // hidden dim
    const float* P0 = g_PT;
    const float* P1 = g_PT + B * FOURD;
    size_t o = (size_t)b * FOURD + j;
    float gi = P0[o]       + P1[o]       + g_bc[j];
    float gf = P0[o + 256] + P1[o + 256] + g_bc[256 + j];
    float gg = P0[o + 512] + P1[o + 512] + g_bc[512 + j];
    float go = P0[o + 768] + P1[o + 768] + g_bc[768 + j];
    float c = sigf(gf) * g_c[t] + sigf(gi) * tanhf(gg);
    float h = sigf(go) * tanhf(c);
    g_c[t] = c;
    g_h[t] = h;
}

// ---------------- fused attention: barrier-free warp-local online softmax ----
__global__ __launch_bounds__(256) void attn_kernel(const float* __restrict__ feat,
                                                   float* __restrict__ qstar) {
    __shared__ float s_m[8], s_s[8];
    __shared__ float s_acc[8][256];
    const int g    = blockIdx.x;
    const int tid  = threadIdx.x;
    const int w    = tid >> 5, lane = tid & 31;
    const int s0 = g_segstart[g];
    const int s1 = g_segstart[g + 1];

    float q[8];
    {
        const float* qp = g_h + (size_t)g * D + lane * 8;
#pragma unroll
        for (int j = 0; j < 8; j++) q[j] = qp[j];
    }

    float m = -1e30f, ss = 0.f;
    float acc[8] = {};

    int i = s0 + w;
    for (; i + 8 < s1; i += 16) {
        const float* pa_ = feat + (size_t)i * D + lane * 8;
        const float* pb_ = feat + (size_t)(i + 8) * D + lane * 8;
        float4 a0 = *(const float4*)(pa_);
        float4 a1 = *(const float4*)(pa_ + 4);
        float4 b0 = *(const float4*)(pb_);
        float4 b1 = *(const float4*)(pb_ + 4);
        float va[8] = {a0.x, a0.y, a0.z, a0.w, a1.x, a1.y, a1.z, a1.w};
        float vb[8] = {b0.x, b0.y, b0.z, b0.w, b1.x, b1.y, b1.z, b1.w};
        float pa = 0.f, pb = 0.f;
#pragma unroll
        for (int j = 0; j < 8; j++) {
            pa = fmaf(va[j], q[j], pa);
            pb = fmaf(vb[j], q[j], pb);
        }
#pragma unroll
        for (int o = 16; o > 0; o >>= 1) {
            pa += __shfl_xor_sync(0xffffffffu, pa, o);
            pb += __shfl_xor_sync(0xffffffffu, pb, o);
        }
        float mn = fmaxf(m, fmaxf(pa, pb));
        float sc = __expf(m - mn);
        float wa = __expf(pa - mn);
        float wb = __expf(pb - mn);
        ss = ss * sc + wa + wb;
#pragma unroll
        for (int j = 0; j < 8; j++)
            acc[j] = fmaf(acc[j], sc, fmaf(wa, va[j], wb * vb[j]));
        m = mn;
    }
    if (i < s1) {
        const float* pa_ = feat + (size_t)i * D + lane * 8;
        float4 a0 = *(const float4*)(pa_);
        float4 a1 = *(const float4*)(pa_ + 4);
        float va[8] = {a0.x, a0.y, a0.z, a0.w, a1.x, a1.y, a1.z, a1.w};
        float pa = 0.f;
#pragma unroll
        for (int j = 0; j < 8; j++) pa = fmaf(va[j], q[j], pa);
#pragma unroll
        for (int o = 16; o > 0; o >>= 1)
            pa += __shfl_xor_sync(0xffffffffu, pa, o);
        float mn = fmaxf(m, pa);
        float sc = __expf(m - mn);
        float wa = __expf(pa - mn);
        ss = ss * sc + wa;
#pragma unroll
        for (int j = 0; j < 8; j++)
            acc[j] = fmaf(acc[j], sc, wa * va[j]);
        m = mn;
    }

    if (lane == 0) { s_m[w] = m; s_s[w] = ss; }
#pragma unroll
    for (int j = 0; j < 8; j += 4)
        *(float4*)&s_acc[w][lane * 8 + j] = make_float4(acc[j], acc[j+1], acc[j+2], acc[j+3]);
    __syncthreads();

    const int d = tid;
    float M = -1e30f;
#pragma unroll
    for (int t = 0; t < 8; t++) M = fmaxf(M, s_m[t]);
    float denom = 0.f, num = 0.f;
#pragma unroll
    for (int t = 0; t < 8; t++) {
        float sc = __expf(s_m[t] - M);
        denom += sc * s_s[t];
        num   += sc * s_acc[t][d];
    }
    float qd = g_h[(size_t)g * D + d];
    float r  = (s1 > s0) ? num / denom : 0.f;
    qstar[(size_t)g * TWO_D + d]     = qd;
    qstar[(size_t)g * TWO_D + D + d] = r;
}

// ---------------- driver ----------------
extern "C" void kernel_launch(void* const* d_in, const int* in_sizes, int n_in,
                              void* d_out, int out_size) {
    const float* feat = (const float*)d_in[0];
    const float* Wih  = (const float*)d_in[1];
    const float* Whh  = (const float*)d_in[2];
    const float* bih  = (const float*)d_in[3];
    const float* bhh  = (const float*)d_in[4];
    const int*   seg  = (const int*)d_in[5];
    const int n = in_sizes[0] / D;
    float* out = (float*)d_out;

    (void)cudaFuncSetAttribute(gemm_mma, cudaFuncAttributeMaxDynamicSharedMemorySize,
                               SMEM_BYTES);

    zero_kernel<<<(B * TWO_D + 255) / 256, 256>>>(out);
    prep_kernel<<<(FOURD * KDIM + 255) / 256, 256>>>(Wih, Whh, bih, bhh);
    segstart_kernel<<<(n + 255) / 256, 256>>>(seg, n);

    for (int it = 0; it < NITER; it++) {
        split_kernel<<<(B * KDIM + 255) / 256, 256>>>(out);
        gemm_mma<<<128, 256, SMEM_BYTES>>>();
        lstm_kernel<<<(B * D + 255) / 256, 256>>>();
        attn_kernel<<<B, 256>>>(feat, out);
    }
}